// round 10
// baseline (speedup 1.0000x reference)
#include <cuda_runtime.h>
#include <cstdint>

// Attention (B,H,S,D)=(256,32,16,64): qk^T/sqrt(8)+1, softmax, JAX threefry
// dropout (key 42, keep 0.7, partitionable XOR-fold), @V.
// Warp-per-head-stream: each warp pipelines NH=4 heads (double-buffered k/q,
// single-buffered v), XOR-swizzled smem, threefry in the load bubble.

#define TPB   64
#define WPB   2                 // warps per CTA
#define NH    4                 // heads per warp (pipelined)
#define NBLK  (8192 / (WPB * NH))
#define ASTR  24                // attn smem row stride (floats)

#define TF_ROUND(r) { x0 += x1; x1 = __funnelshift_l(x1, x1, (r)); x1 ^= x0; }

static __device__ __forceinline__ uint32_t jax_threefry_bits(uint32_t idx) {
    const uint32_t k0 = 0u, k1 = 42u, k2 = 0u ^ 42u ^ 0x1BD11BDAu;
    uint32_t x0 = 0u + k0;
    uint32_t x1 = idx + k1;
    TF_ROUND(13) TF_ROUND(15) TF_ROUND(26) TF_ROUND(6)
    x0 += k1; x1 += k2 + 1u;
    TF_ROUND(17) TF_ROUND(29) TF_ROUND(16) TF_ROUND(24)
    x0 += k2; x1 += k0 + 2u;
    TF_ROUND(13) TF_ROUND(15) TF_ROUND(26) TF_ROUND(6)
    x0 += k0; x1 += k1 + 3u;
    TF_ROUND(17) TF_ROUND(29) TF_ROUND(16) TF_ROUND(24)
    x0 += k1; x1 += k2 + 4u;
    TF_ROUND(13) TF_ROUND(15) TF_ROUND(26) TF_ROUND(6)
    x0 += k2; x1 += k0 + 5u;
    return x0 ^ x1;             // partitionable mode XOR fold
}

static __device__ __forceinline__ float drop_scale(uint32_t idx) {
    uint32_t bits = jax_threefry_bits(idx);
    float u = __uint_as_float((bits >> 9) | 0x3f800000u) - 1.0f;
    return (u < 0.7f) ? (1.0f / 0.7f) : 0.0f;
}

static __device__ __forceinline__ float dot4(float4 a, float4 b) {
    return a.x * b.x + a.y * b.y + a.z * b.z + a.w * b.w;
}

static __device__ __forceinline__ void cp_async16(void* smem_dst, const void* gsrc) {
    uint32_t s = (uint32_t)__cvta_generic_to_shared(smem_dst);
    asm volatile("cp.async.cg.shared.global [%0], [%1], 16;\n"
                 :: "r"(s), "l"(gsrc) : "memory");
}
#define CP_COMMIT()  asm volatile("cp.async.commit_group;\n" ::: "memory")
#define CP_WAIT(n)   asm volatile("cp.async.wait_group %0;\n" :: "n"(n) : "memory")

__global__ __launch_bounds__(TPB) void attn_drop_kernel(
    const float4* __restrict__ qg,
    const float4* __restrict__ kg,
    const float4* __restrict__ vg,
    float4* __restrict__ og)
{
    // XOR-swizzled (col ^ row) q/k tiles, double buffered; linear v; padded attn.
    __shared__ float4 sq[WPB][2][256];
    __shared__ float4 sk[WPB][2][256];
    __shared__ float4 sv[WPB][256];
    __shared__ float  sattn[WPB][16 * ASTR];

    const int w    = threadIdx.x >> 5;
    const int lane = threadIdx.x & 31;
    const int gw   = blockIdx.x * WPB + w;      // global warp id
    const int rg   = lane >> 3;                  // rows rg^(4j), j=0..3
    const int c2   = lane & 7;                   // cols c2, c2+8

    // staging indices (8 iters x 32 lanes = 256 float4)
    int sidx[8], gidx[8];
    #pragma unroll
    for (int it = 0; it < 8; ++it) {
        int idx = lane + 32 * it;
        int r = idx >> 4, c = idx & 15;
        gidx[it] = idx;
        sidx[it] = r * 16 + (c ^ r);            // XOR swizzle
    }

    // ---- preamble: stage head 0 ----
    int base0 = (gw * NH) << 8;
    #pragma unroll
    for (int it = 0; it < 8; ++it) {
        cp_async16(&sk[w][0][sidx[it]], &kg[base0 + gidx[it]]);
        cp_async16(&sq[w][0][sidx[it]], &qg[base0 + gidx[it]]);
    }
    CP_COMMIT();
    #pragma unroll
    for (int it = 0; it < 8; ++it)
        cp_async16(&sv[w][gidx[it]], &vg[base0 + gidx[it]]);
    CP_COMMIT();

    #pragma unroll
    for (int h = 0; h < NH; ++h) {
        const int cur  = h & 1, nxt = cur ^ 1;
        const int base = (gw * NH + h) << 8;

        // ---- threefry for this head (overlaps in-flight loads) ----
        float drop[4][2];
        #pragma unroll
        for (int j = 0; j < 4; ++j) {
            uint32_t ib = (uint32_t)(base + (rg ^ (4 * j)) * 16 + c2);
            drop[j][0] = drop_scale(ib);
            drop[j][1] = drop_scale(ib + 8u);
        }

        // kq(h) ready (v(h) may still be in flight)
        CP_WAIT(1);
        __syncwarp();

        // ---- scores: rows rg^(4j), cols c2 & c2+8 ----
        float s[4][2] = {{0,0},{0,0},{0,0},{0,0}};
        #pragma unroll
        for (int i = 0; i < 16; ++i) {
            const int ic = i ^ c2;
            float4 b0 = sk[w][cur][c2 * 16 + ic];
            float4 b1 = sk[w][cur][(c2 + 8) * 16 + (ic ^ 8)];
            const int ir = i ^ rg;
            #pragma unroll
            for (int j = 0; j < 4; ++j) {
                float4 a = sq[w][cur][(rg ^ (4 * j)) * 16 + (ir ^ (4 * j))];
                s[j][0] += dot4(a, b0);
                s[j][1] += dot4(a, b1);
            }
        }

        const float SCALE = 0.35355339059327373f;
        #pragma unroll
        for (int j = 0; j < 4; ++j) {
            int row = rg ^ (4 * j);
            float s0 = s[j][0] * SCALE + 1.0f;
            float s1 = s[j][1] * SCALE + 1.0f;
            float m = fmaxf(s0, s1);
            #pragma unroll
            for (int o = 4; o; o >>= 1)
                m = fmaxf(m, __shfl_xor_sync(0xffffffffu, m, o, 8));
            float e0 = __expf(s0 - m), e1 = __expf(s1 - m);
            float t = e0 + e1;
            #pragma unroll
            for (int o = 4; o; o >>= 1)
                t += __shfl_xor_sync(0xffffffffu, t, o, 8);
            float inv = __fdividef(1.0f, t);
            sattn[w][row * ASTR + c2]     = e0 * inv * drop[j][0];
            sattn[w][row * ASTR + c2 + 8] = e1 * inv * drop[j][1];
        }

        // ---- prefetch kq(h+1) into the other buffer ----
        if (h < NH - 1) {
            int nbase = base + 256;
            #pragma unroll
            for (int it = 0; it < 8; ++it) {
                cp_async16(&sk[w][nxt][sidx[it]], &kg[nbase + gidx[it]]);
                cp_async16(&sq[w][nxt][sidx[it]], &qg[nbase + gidx[it]]);
            }
            CP_COMMIT();
            CP_WAIT(1);        // v(h) done; kq(h+1) may remain in flight
        } else {
            CP_WAIT(0);        // last head: drain everything
        }
        __syncwarp();

        // ---- AV: one pass ----
        float4 acc[4][2];
        #pragma unroll
        for (int j = 0; j < 4; ++j) {
            acc[j][0] = make_float4(0, 0, 0, 0);
            acc[j][1] = make_float4(0, 0, 0, 0);
        }
        #pragma unroll
        for (int uc = 0; uc < 4; ++uc) {
            float4 a4[4];
            #pragma unroll
            for (int j = 0; j < 4; ++j)
                a4[j] = *(const float4*)&sattn[w][(rg ^ (4 * j)) * ASTR + 4 * uc];
            #pragma unroll
            for (int t = 0; t < 4; ++t) {
                int u = 4 * uc + t;
                float4 v0 = sv[w][u * 16 + c2];
                float4 v1 = sv[w][u * 16 + c2 + 8];
                #pragma unroll
                for (int j = 0; j < 4; ++j) {
                    float a = (t == 0) ? a4[j].x : (t == 1) ? a4[j].y
                            : (t == 2) ? a4[j].z : a4[j].w;
                    acc[j][0].x += a * v0.x; acc[j][0].y += a * v0.y;
                    acc[j][0].z += a * v0.z; acc[j][0].w += a * v0.w;
                    acc[j][1].x += a * v1.x; acc[j][1].y += a * v1.y;
                    acc[j][1].z += a * v1.z; acc[j][1].w += a * v1.w;
                }
            }
        }
        __syncwarp();          // all lanes done reading sv before refill

        // ---- prefetch v(h+1) into the (single) v buffer ----
        if (h < NH - 1) {
            int nbase = base + 256;
            #pragma unroll
            for (int it = 0; it < 8; ++it)
                cp_async16(&sv[w][gidx[it]], &vg[nbase + gidx[it]]);
            CP_COMMIT();
        }

        // ---- store out ----
        #pragma unroll
        for (int j = 0; j < 4; ++j) {
            int row = rg ^ (4 * j);
            og[base + row * 16 + c2]     = acc[j][0];
            og[base + row * 16 + c2 + 8] = acc[j][1];
        }
    }
}

extern "C" void kernel_launch(void* const* d_in, const int* in_sizes, int n_in,
                              void* d_out, int out_size) {
    attn_drop_kernel<<<NBLK, TPB>>>(
        (const float4*)d_in[0],   // q
        (const float4*)d_in[1],   // k
        (const float4*)d_in[2],   // v
        (float4*)d_out);
}

// round 15
// speedup vs baseline: 1.2574x; 1.2574x over previous
#include <cuda_runtime.h>
#include <cstdint>

// Attention (B,H,S,D)=(256,32,16,64): qk^T/sqrt(8)+1, softmax, JAX threefry
// dropout (key 42, keep 0.7, partitionable XOR-fold), @V.
// Half-head per warp (8 rows x 16 cols, 2x2/lane). Each warp stages full k,v
// + its q half (k/v dup absorbed by L2). cp.async split groups, threefry in
// the DRAM bubble, XOR-swizzled smem, syncwarp-only.

#define TPB   64                // 2 warps = 1 head
#define NBLK  8192
#define ASTR  20                // attn smem row stride (floats)

#define TF_ROUND(r) { x0 += x1; x1 = __funnelshift_l(x1, x1, (r)); x1 ^= x0; }

static __device__ __forceinline__ uint32_t jax_threefry_bits(uint32_t idx) {
    const uint32_t k0 = 0u, k1 = 42u, k2 = 0u ^ 42u ^ 0x1BD11BDAu;
    uint32_t x0 = 0u + k0;
    uint32_t x1 = idx + k1;
    TF_ROUND(13) TF_ROUND(15) TF_ROUND(26) TF_ROUND(6)
    x0 += k1; x1 += k2 + 1u;
    TF_ROUND(17) TF_ROUND(29) TF_ROUND(16) TF_ROUND(24)
    x0 += k2; x1 += k0 + 2u;
    TF_ROUND(13) TF_ROUND(15) TF_ROUND(26) TF_ROUND(6)
    x0 += k0; x1 += k1 + 3u;
    TF_ROUND(17) TF_ROUND(29) TF_ROUND(16) TF_ROUND(24)
    x0 += k1; x1 += k2 + 4u;
    TF_ROUND(13) TF_ROUND(15) TF_ROUND(26) TF_ROUND(6)
    x0 += k2; x1 += k0 + 5u;
    return x0 ^ x1;             // partitionable mode XOR fold
}

static __device__ __forceinline__ float drop_scale(uint32_t idx) {
    uint32_t bits = jax_threefry_bits(idx);
    float u = __uint_as_float((bits >> 9) | 0x3f800000u) - 1.0f;
    return (u < 0.7f) ? (1.0f / 0.7f) : 0.0f;
}

static __device__ __forceinline__ float dot4(float4 a, float4 b) {
    return a.x * b.x + a.y * b.y + a.z * b.z + a.w * b.w;
}

static __device__ __forceinline__ void cp_async16(void* smem_dst, const void* gsrc) {
    uint32_t s = (uint32_t)__cvta_generic_to_shared(smem_dst);
    asm volatile("cp.async.cg.shared.global [%0], [%1], 16;\n"
                 :: "r"(s), "l"(gsrc) : "memory");
}
#define CP_COMMIT()  asm volatile("cp.async.commit_group;\n" ::: "memory")
#define CP_WAIT(n)   asm volatile("cp.async.wait_group %0;\n" :: "n"(n) : "memory")

__global__ __launch_bounds__(TPB, 10) void attn_drop_kernel(
    const float4* __restrict__ qg,
    const float4* __restrict__ kg,
    const float4* __restrict__ vg,
    float4* __restrict__ og)
{
    // per-warp buffers (2 warps/CTA, fully independent)
    __shared__ float4 sk[2][256];        // k[t][d4], XOR-swizzled (d4 ^ t)
    __shared__ float4 sq[2][128];        // q half: 8 rows, XOR-swizzled
    __shared__ float4 sv[2][256];        // v[u][d4], linear
    __shared__ float  sattn[2][8 * ASTR];

    const int w     = threadIdx.x >> 5;
    const int lane  = threadIdx.x & 31;
    const int bh    = blockIdx.x;
    const int base  = bh << 8;           // float4 offset of this head
    const int rbase = w * 8;             // this warp's 8 rows
    const int rp    = lane >> 3;         // row pair 0..3 -> local rows 2rp,2rp+1
    const int c2    = lane & 7;          // cols c2, c2+8

    // ---- group 0: full k + this warp's q half ----
    #pragma unroll
    for (int it = 0; it < 8; ++it) {
        int idx = lane + 32 * it;        // 0..255
        int r = idx >> 4, c = idx & 15;
        cp_async16(&sk[w][r * 16 + (c ^ r)], &kg[base + idx]);
    }
    #pragma unroll
    for (int it = 0; it < 4; ++it) {
        int idx = lane + 32 * it;        // 0..127
        int r = idx >> 4, c = idx & 15;  // r = local row 0..7
        cp_async16(&sq[w][r * 16 + (c ^ r)], &qg[base + (rbase + r) * 16 + c]);
    }
    CP_COMMIT();
    // ---- group 1: full v ----
    #pragma unroll
    for (int it = 0; it < 8; ++it) {
        int idx = lane + 32 * it;
        cp_async16(&sv[w][idx], &vg[base + idx]);
    }
    CP_COMMIT();

    // ---- threefry dropout scales (index-only; fills the DRAM bubble) ----
    float drop[2][2];
    #pragma unroll
    for (int j = 0; j < 2; ++j) {
        uint32_t ib = (uint32_t)(base + (rbase + 2 * rp + j) * 16 + c2);
        drop[j][0] = drop_scale(ib);
        drop[j][1] = drop_scale(ib + 8u);
    }

    CP_WAIT(1);                          // k + q ready (v may be in flight)
    __syncwarp();

    // ---- scores: local rows 2rp, 2rp+1; cols c2, c2+8 ----
    float s[2][2] = {{0,0},{0,0}};
    #pragma unroll
    for (int i = 0; i < 16; ++i) {
        float4 b0 = sk[w][c2 * 16 + (i ^ c2)];
        float4 b1 = sk[w][(c2 + 8) * 16 + (i ^ (c2 + 8))];
        #pragma unroll
        for (int j = 0; j < 2; ++j) {
            int lr = 2 * rp + j;
            float4 a = sq[w][lr * 16 + (i ^ lr)];
            s[j][0] += dot4(a, b0);
            s[j][1] += dot4(a, b1);
        }
    }

    const float SCALE = 0.35355339059327373f;
    #pragma unroll
    for (int j = 0; j < 2; ++j) {
        int lr = 2 * rp + j;
        float s0 = s[j][0] * SCALE + 1.0f;
        float s1 = s[j][1] * SCALE + 1.0f;
        float m = fmaxf(s0, s1);
        #pragma unroll
        for (int o = 4; o; o >>= 1)
            m = fmaxf(m, __shfl_xor_sync(0xffffffffu, m, o, 8));
        float e0 = __expf(s0 - m), e1 = __expf(s1 - m);
        float t = e0 + e1;
        #pragma unroll
        for (int o = 4; o; o >>= 1)
            t += __shfl_xor_sync(0xffffffffu, t, o, 8);
        float inv = __fdividef(1.0f, t);
        sattn[w][lr * ASTR + c2]     = e0 * inv * drop[j][0];
        sattn[w][lr * ASTR + c2 + 8] = e1 * inv * drop[j][1];
    }

    CP_WAIT(0);                          // v ready
    __syncwarp();

    // ---- AV: local rows 2rp,2rp+1 x col4s c2, c2+8 ----
    float4 acc[2][2];
    #pragma unroll
    for (int j = 0; j < 2; ++j) {
        acc[j][0] = make_float4(0, 0, 0, 0);
        acc[j][1] = make_float4(0, 0, 0, 0);
    }
    #pragma unroll
    for (int uc = 0; uc < 4; ++uc) {
        float4 a4[2];
        #pragma unroll
        for (int j = 0; j < 2; ++j)
            a4[j] = *(const float4*)&sattn[w][(2 * rp + j) * ASTR + 4 * uc];
        #pragma unroll
        for (int t = 0; t < 4; ++t) {
            int u = 4 * uc + t;
            float4 v0 = sv[w][u * 16 + c2];
            float4 v1 = sv[w][u * 16 + c2 + 8];
            #pragma unroll
            for (int j = 0; j < 2; ++j) {
                float a = (t == 0) ? a4[j].x : (t == 1) ? a4[j].y
                        : (t == 2) ? a4[j].z : a4[j].w;
                acc[j][0].x += a * v0.x; acc[j][0].y += a * v0.y;
                acc[j][0].z += a * v0.z; acc[j][0].w += a * v0.w;
                acc[j][1].x += a * v1.x; acc[j][1].y += a * v1.y;
                acc[j][1].z += a * v1.z; acc[j][1].w += a * v1.w;
            }
        }
    }

    #pragma unroll
    for (int j = 0; j < 2; ++j) {
        int row = rbase + 2 * rp + j;
        og[base + row * 16 + c2]     = acc[j][0];
        og[base + row * 16 + c2 + 8] = acc[j][1];
    }
}

extern "C" void kernel_launch(void* const* d_in, const int* in_sizes, int n_in,
                              void* d_out, int out_size) {
    attn_drop_kernel<<<NBLK, TPB>>>(
        (const float4*)d_in[0],   // q
        (const float4*)d_in[1],   // k
        (const float4*)d_in[2],   // v
        (float4*)d_out);
}

// round 16
// speedup vs baseline: 1.9190x; 1.5262x over previous
#include <cuda_runtime.h>
#include <cstdint>

// Attention (B,H,S,D)=(256,32,16,64): qk^T/sqrt(8)+1, softmax, JAX threefry
// dropout (key 42, keep 0.7, partitionable XOR-fold), @V.
// CTA = 1 head = 64 threads: k/q/v staged ONCE per CTA via cp.async (split
// groups), each warp computes 8 rows (2x2/lane), threefry in the DRAM bubble,
// XOR-swizzled smem, two cheap __syncthreads.

#define TPB   64
#define NBLK  8192
#define ASTR  20                // attn smem row stride (floats)

#define TF_ROUND(r) { x0 += x1; x1 = __funnelshift_l(x1, x1, (r)); x1 ^= x0; }

static __device__ __forceinline__ uint32_t jax_threefry_bits(uint32_t idx) {
    const uint32_t k0 = 0u, k1 = 42u, k2 = 0u ^ 42u ^ 0x1BD11BDAu;
    uint32_t x0 = 0u + k0;
    uint32_t x1 = idx + k1;
    TF_ROUND(13) TF_ROUND(15) TF_ROUND(26) TF_ROUND(6)
    x0 += k1; x1 += k2 + 1u;
    TF_ROUND(17) TF_ROUND(29) TF_ROUND(16) TF_ROUND(24)
    x0 += k2; x1 += k0 + 2u;
    TF_ROUND(13) TF_ROUND(15) TF_ROUND(26) TF_ROUND(6)
    x0 += k0; x1 += k1 + 3u;
    TF_ROUND(17) TF_ROUND(29) TF_ROUND(16) TF_ROUND(24)
    x0 += k1; x1 += k2 + 4u;
    TF_ROUND(13) TF_ROUND(15) TF_ROUND(26) TF_ROUND(6)
    x0 += k2; x1 += k0 + 5u;
    return x0 ^ x1;             // partitionable mode XOR fold
}

static __device__ __forceinline__ float drop_scale(uint32_t idx) {
    uint32_t bits = jax_threefry_bits(idx);
    float u = __uint_as_float((bits >> 9) | 0x3f800000u) - 1.0f;
    return (u < 0.7f) ? (1.0f / 0.7f) : 0.0f;
}

static __device__ __forceinline__ float dot4(float4 a, float4 b) {
    return a.x * b.x + a.y * b.y + a.z * b.z + a.w * b.w;
}

static __device__ __forceinline__ void cp_async16(void* smem_dst, const void* gsrc) {
    uint32_t s = (uint32_t)__cvta_generic_to_shared(smem_dst);
    asm volatile("cp.async.cg.shared.global [%0], [%1], 16;\n"
                 :: "r"(s), "l"(gsrc) : "memory");
}
#define CP_COMMIT()  asm volatile("cp.async.commit_group;\n" ::: "memory")
#define CP_WAIT(n)   asm volatile("cp.async.wait_group %0;\n" :: "n"(n) : "memory")

__global__ __launch_bounds__(TPB, 16) void attn_drop_kernel(
    const float4* __restrict__ qg,
    const float4* __restrict__ kg,
    const float4* __restrict__ vg,
    float4* __restrict__ og)
{
    __shared__ float4 sk[256];           // k[t][d4], XOR-swizzled (d4 ^ t)
    __shared__ float4 sq[256];           // q[s][d4], XOR-swizzled
    __shared__ float4 sv[256];           // v[u][d4], linear
    __shared__ float  sattn[16 * ASTR];  // attn[s][t]

    const int tid   = threadIdx.x;
    const int w     = tid >> 5;
    const int lane  = tid & 31;
    const int base  = blockIdx.x << 8;   // float4 offset of this head
    const int rbase = w * 8;             // this warp's 8 rows
    const int rp    = lane >> 3;         // row pair 0..3 -> local rows 2rp,2rp+1
    const int c2    = lane & 7;          // cols c2, c2+8

    // ---- group 0: k + q, staged once by the whole CTA ----
    #pragma unroll
    for (int it = 0; it < 4; ++it) {
        int idx = tid + 64 * it;         // 0..255
        int r = idx >> 4, c = idx & 15;
        int sw = r * 16 + (c ^ r);
        cp_async16(&sk[sw], &kg[base + idx]);
        cp_async16(&sq[sw], &qg[base + idx]);
    }
    CP_COMMIT();
    // ---- group 1: v ----
    #pragma unroll
    for (int it = 0; it < 4; ++it) {
        int idx = tid + 64 * it;
        cp_async16(&sv[idx], &vg[base + idx]);
    }
    CP_COMMIT();

    // ---- threefry dropout scales (index-only; fills the DRAM bubble) ----
    float drop[2][2];
    #pragma unroll
    for (int j = 0; j < 2; ++j) {
        uint32_t ib = (uint32_t)(base + (rbase + 2 * rp + j) * 16 + c2);
        drop[j][0] = drop_scale(ib);
        drop[j][1] = drop_scale(ib + 8u);
    }

    CP_WAIT(1);                          // k + q landed (per-thread)
    __syncthreads();                     // CTA-wide visibility

    // ---- scores: global rows rbase+2rp, rbase+2rp+1; cols c2, c2+8 ----
    float s[2][2] = {{0,0},{0,0}};
    #pragma unroll
    for (int i = 0; i < 16; ++i) {
        float4 b0 = sk[c2 * 16 + (i ^ c2)];
        float4 b1 = sk[(c2 + 8) * 16 + (i ^ (c2 + 8))];
        #pragma unroll
        for (int j = 0; j < 2; ++j) {
            int gr = rbase + 2 * rp + j;
            float4 a = sq[gr * 16 + (i ^ gr)];
            s[j][0] += dot4(a, b0);
            s[j][1] += dot4(a, b1);
        }
    }

    const float SCALE = 0.35355339059327373f;
    #pragma unroll
    for (int j = 0; j < 2; ++j) {
        int gr = rbase + 2 * rp + j;
        float s0 = s[j][0] * SCALE + 1.0f;
        float s1 = s[j][1] * SCALE + 1.0f;
        float m = fmaxf(s0, s1);
        #pragma unroll
        for (int o = 4; o; o >>= 1)
            m = fmaxf(m, __shfl_xor_sync(0xffffffffu, m, o, 8));
        float e0 = __expf(s0 - m), e1 = __expf(s1 - m);
        float t = e0 + e1;
        #pragma unroll
        for (int o = 4; o; o >>= 1)
            t += __shfl_xor_sync(0xffffffffu, t, o, 8);
        float inv = __fdividef(1.0f, t);
        sattn[gr * ASTR + c2]     = e0 * inv * drop[j][0];
        sattn[gr * ASTR + c2 + 8] = e1 * inv * drop[j][1];
    }

    CP_WAIT(0);                          // v landed (per-thread)
    __syncthreads();                     // CTA-wide visibility (v + attn)

    // ---- AV: rows rbase+2rp(+1) x col4s c2, c2+8 ----
    float4 acc[2][2];
    #pragma unroll
    for (int j = 0; j < 2; ++j) {
        acc[j][0] = make_float4(0, 0, 0, 0);
        acc[j][1] = make_float4(0, 0, 0, 0);
    }
    #pragma unroll
    for (int uc = 0; uc < 4; ++uc) {
        float4 a4[2];
        #pragma unroll
        for (int j = 0; j < 2; ++j)
            a4[j] = *(const float4*)&sattn[(rbase + 2 * rp + j) * ASTR + 4 * uc];
        #pragma unroll
        for (int t = 0; t < 4; ++t) {
            int u = 4 * uc + t;
            float4 v0 = sv[u * 16 + c2];
            float4 v1 = sv[u * 16 + c2 + 8];
            #pragma unroll
            for (int j = 0; j < 2; ++j) {
                float a = (t == 0) ? a4[j].x : (t == 1) ? a4[j].y
                        : (t == 2) ? a4[j].z : a4[j].w;
                acc[j][0].x += a * v0.x; acc[j][0].y += a * v0.y;
                acc[j][0].z += a * v0.z; acc[j][0].w += a * v0.w;
                acc[j][1].x += a * v1.x; acc[j][1].y += a * v1.y;
                acc[j][1].z += a * v1.z; acc[j][1].w += a * v1.w;
            }
        }
    }

    #pragma unroll
    for (int j = 0; j < 2; ++j) {
        int gr = rbase + 2 * rp + j;
        og[base + gr * 16 + c2]     = acc[j][0];
        og[base + gr * 16 + c2 + 8] = acc[j][1];
    }
}

extern "C" void kernel_launch(void* const* d_in, const int* in_sizes, int n_in,
                              void* d_out, int out_size) {
    attn_drop_kernel<<<NBLK, TPB>>>(
        (const float4*)d_in[0],   // q
        (const float4*)d_in[1],   // k
        (const float4*)d_in[2],   // v
        (float4*)d_out);
}